// round 7
// baseline (speedup 1.0000x reference)
#include <cuda_runtime.h>
#include <math.h>
#include <stdint.h>

#define NB 8
#define NT 64
#define NN 512
#define NH 256
#define NOUT 512
#define NFLEN 24

// ---------------- device scratch (no allocations allowed) ----------------
__device__ float d_xg[NB * NT * NN];          // GAT output  [B,T,N]
__device__ float d_G[NB * NT * 4 * NH];       // enc input preacts (+bias)
__device__ float d_Weffc[4 * NH * NH];        // dec_Wih @ fc_W + decWhh
__device__ float d_db0[4 * NH];               // dec bias (dt==0)
__device__ float d_dbE[4 * NH];               // dec bias + decWih@fcb

// ============================= GAT kernel =================================
__global__ __launch_bounds__(512) void gat_kernel(const float* __restrict__ x,
                                                  const float* __restrict__ gatW,
                                                  const float* __restrict__ gata) {
    __shared__ float  sk[512];
    __shared__ float  sf[512];
    __shared__ float4 ssum[512];
    __shared__ float  sred[16];
    __shared__ float4 swt[16];
    __shared__ float4 swo[16];

    int bt = blockIdx.x, tid = threadIdx.x;
    int lane = tid & 31, wid = tid >> 5;
    float W = gatW[0], a0 = gata[0], a1 = gata[1];
    float fi = x[bt * NN + tid] * W;
    float v = a1 * fi;

    float m = v;
    #pragma unroll
    for (int s = 16; s; s >>= 1) m = fmaxf(m, __shfl_xor_sync(0xffffffffu, m, s));
    if (lane == 0) sred[wid] = m;
    __syncthreads();
    if (tid < 32) {
        float t2 = (tid < 16) ? sred[tid] : -3.4e38f;
        #pragma unroll
        for (int s = 8; s; s >>= 1) t2 = fmaxf(t2, __shfl_xor_sync(0xffffffffu, t2, s));
        if (tid == 0) sred[0] = t2;
    }
    sk[tid] = v;
    sf[tid] = fi;
    __syncthreads();
    float vmax = sred[0];

    for (int k = 2; k <= 512; k <<= 1) {
        for (int j = k >> 1; j > 0; j >>= 1) {
            int ixj = tid ^ j;
            if (ixj > tid) {
                float ka = sk[tid], kb = sk[ixj];
                bool up = ((tid & k) == 0);
                if ((ka > kb) == up) {
                    sk[tid] = kb; sk[ixj] = ka;
                    float t = sf[tid]; sf[tid] = sf[ixj]; sf[ixj] = t;
                }
            }
            __syncthreads();
        }
    }

    float vs = sk[tid], fs = sf[tid];
    float p1 = __expf(vs - vmax);
    float p2 = __expf(0.2f * (vs - vmax));
    float4 pl = make_float4(p1, p2, fs * p1, fs * p2);

    float4 s4 = pl;
    #pragma unroll
    for (int off = 1; off < 32; off <<= 1) {
        float nx = __shfl_up_sync(0xffffffffu, s4.x, off);
        float ny = __shfl_up_sync(0xffffffffu, s4.y, off);
        float nz = __shfl_up_sync(0xffffffffu, s4.z, off);
        float nw = __shfl_up_sync(0xffffffffu, s4.w, off);
        if (lane >= off) { s4.x += nx; s4.y += ny; s4.z += nz; s4.w += nw; }
    }
    if (lane == 31) swt[wid] = s4;
    __syncthreads();
    if (tid < 16) {
        float4 t4 = swt[tid];
        float4 c4 = t4;
        #pragma unroll
        for (int off = 1; off < 16; off <<= 1) {
            float nx = __shfl_up_sync(0x0000ffffu, c4.x, off);
            float ny = __shfl_up_sync(0x0000ffffu, c4.y, off);
            float nz = __shfl_up_sync(0x0000ffffu, c4.z, off);
            float nw = __shfl_up_sync(0x0000ffffu, c4.w, off);
            if (tid >= off) { c4.x += nx; c4.y += ny; c4.z += nz; c4.w += nw; }
        }
        swo[tid] = make_float4(c4.x - t4.x, c4.y - t4.y, c4.z - t4.z, c4.w - t4.w);
    }
    __syncthreads();
    float4 wo = swo[wid];
    float4 excl = make_float4(s4.x - pl.x + wo.x, s4.y - pl.y + wo.y,
                              s4.z - pl.z + wo.z, s4.w - pl.w + wo.w);
    ssum[tid] = excl;
    __syncthreads();
    float4 T = make_float4(swo[15].x + swt[15].x, swo[15].y + swt[15].y,
                           swo[15].z + swt[15].z, swo[15].w + swt[15].w);

    float c = a0 * fi, thr = -c;
    int lo = 0, hi = 512;
    #pragma unroll
    for (int it = 0; it < 9; it++) {
        int mid = (lo + hi) >> 1;
        bool g = sk[mid] > thr;
        hi = g ? mid : hi;
        lo = g ? lo : mid + 1;
    }
    float4 E = (lo < 512) ? ssum[lo] : T;
    float A  = T.z - E.z;
    float Cs = T.x - E.x;
    float D  = E.y;
    float Bs = E.w;

    float s = c + vmax;
    float M = s > 0.f ? s : 0.2f * s;
    float alpha = __expf(s - M);
    float beta  = __expf(0.2f * s - M);
    float r = (alpha * A + beta * Bs) / (alpha * Cs + beta * D);
    d_xg[bt * NN + tid] = r > 0.f ? r : 0.f;
}

// ======================= enc input GEMM (+bias) ===========================
// G[m,r] = xg[m,:] . Wih[r,:] + b ;  M=512, R=1024, K=512
// 64x64 tiles, K-chunks of 32, k-major smem, double-buffered global loads.
__global__ __launch_bounds__(256) void enc_gemm(const float* __restrict__ Wih,
                                                const float* __restrict__ bih,
                                                const float* __restrict__ bhh) {
    __shared__ float As[2][32][68];
    __shared__ float Bs[2][32][68];
    const int tid = threadIdx.x;
    const int tx = tid & 15, ty = tid >> 4;
    const int mBase = blockIdx.y * 64, rBase = blockIdx.x * 64;
    const int lm = tid >> 3, lk = (tid & 7) * 4;
    float acc[4][4] = {};
    float4 ra[2], rb[2];

    // preload chunk 0 directly to smem
    #pragma unroll
    for (int h = 0; h < 2; h++) {
        int mm = lm + h * 32;
        float4 av = *(const float4*)&d_xg[(mBase + mm) * 512 + lk];
        As[0][lk + 0][mm] = av.x; As[0][lk + 1][mm] = av.y;
        As[0][lk + 2][mm] = av.z; As[0][lk + 3][mm] = av.w;
        float4 bv = *(const float4*)&Wih[(rBase + mm) * 512 + lk];
        Bs[0][lk + 0][mm] = bv.x; Bs[0][lk + 1][mm] = bv.y;
        Bs[0][lk + 2][mm] = bv.z; Bs[0][lk + 3][mm] = bv.w;
    }
    __syncthreads();

    #pragma unroll 1
    for (int cI = 0; cI < 16; cI++) {
        int buf = cI & 1;
        if (cI < 15) {
            int k0 = (cI + 1) * 32;
            #pragma unroll
            for (int h = 0; h < 2; h++) {
                int mm = lm + h * 32;
                ra[h] = *(const float4*)&d_xg[(mBase + mm) * 512 + k0 + lk];
                rb[h] = *(const float4*)&Wih[(rBase + mm) * 512 + k0 + lk];
            }
        }
        #pragma unroll
        for (int kk = 0; kk < 32; kk++) {
            float4 a = *(const float4*)&As[buf][kk][ty * 4];
            float4 bq = *(const float4*)&Bs[buf][kk][tx * 4];
            acc[0][0] = fmaf(a.x, bq.x, acc[0][0]); acc[0][1] = fmaf(a.x, bq.y, acc[0][1]);
            acc[0][2] = fmaf(a.x, bq.z, acc[0][2]); acc[0][3] = fmaf(a.x, bq.w, acc[0][3]);
            acc[1][0] = fmaf(a.y, bq.x, acc[1][0]); acc[1][1] = fmaf(a.y, bq.y, acc[1][1]);
            acc[1][2] = fmaf(a.y, bq.z, acc[1][2]); acc[1][3] = fmaf(a.y, bq.w, acc[1][3]);
            acc[2][0] = fmaf(a.z, bq.x, acc[2][0]); acc[2][1] = fmaf(a.z, bq.y, acc[2][1]);
            acc[2][2] = fmaf(a.z, bq.z, acc[2][2]); acc[2][3] = fmaf(a.z, bq.w, acc[2][3]);
            acc[3][0] = fmaf(a.w, bq.x, acc[3][0]); acc[3][1] = fmaf(a.w, bq.y, acc[3][1]);
            acc[3][2] = fmaf(a.w, bq.z, acc[3][2]); acc[3][3] = fmaf(a.w, bq.w, acc[3][3]);
        }
        if (cI < 15) {
            __syncthreads();
            int nb = buf ^ 1;
            #pragma unroll
            for (int h = 0; h < 2; h++) {
                int mm = lm + h * 32;
                As[nb][lk + 0][mm] = ra[h].x; As[nb][lk + 1][mm] = ra[h].y;
                As[nb][lk + 2][mm] = ra[h].z; As[nb][lk + 3][mm] = ra[h].w;
                Bs[nb][lk + 0][mm] = rb[h].x; Bs[nb][lk + 1][mm] = rb[h].y;
                Bs[nb][lk + 2][mm] = rb[h].z; Bs[nb][lk + 3][mm] = rb[h].w;
            }
            __syncthreads();
        }
    }
    #pragma unroll
    for (int i = 0; i < 4; i++) {
        int mm = mBase + ty * 4 + i;
        #pragma unroll
        for (int j = 0; j < 4; j++) {
            int r = rBase + tx * 4 + j;
            d_G[mm * 1024 + r] = acc[i][j] + bih[r] + bhh[r];
        }
    }
}

// ====== Weffc GEMM: dec_Wih[1024,512] @ fc_W[512,256] + decWhh ============
// 32(r) x 64(k) tiles, o-chunks of 32, double-buffered. grid (4,32)=128.
__global__ __launch_bounds__(256) void wef_gemm(const float* __restrict__ decWih,
                                                const float* __restrict__ fcW,
                                                const float* __restrict__ decWhh) {
    __shared__ float As[2][32][36];
    __shared__ float Bs[2][32][68];
    const int tid = threadIdx.x;
    const int tx = tid & 15, ty = tid >> 4;
    const int kBase = blockIdx.x * 64, rBase = blockIdx.y * 32;
    const int lr = tid >> 3, lo = (tid & 7) * 4;
    float acc[2][4] = {};
    float4 ra, rb0, rb1;

    {
        float4 av = *(const float4*)&decWih[(rBase + lr) * 512 + lo];
        As[0][lo + 0][lr] = av.x; As[0][lo + 1][lr] = av.y;
        As[0][lo + 2][lr] = av.z; As[0][lo + 3][lr] = av.w;
        *(float4*)&Bs[0][lr][lo] = *(const float4*)&fcW[lr * 256 + kBase + lo];
        *(float4*)&Bs[0][lr][lo + 32] = *(const float4*)&fcW[lr * 256 + kBase + lo + 32];
    }
    __syncthreads();

    #pragma unroll 1
    for (int cI = 0; cI < 16; cI++) {
        int buf = cI & 1;
        if (cI < 15) {
            int o0 = (cI + 1) * 32;
            ra  = *(const float4*)&decWih[(rBase + lr) * 512 + o0 + lo];
            rb0 = *(const float4*)&fcW[(o0 + lr) * 256 + kBase + lo];
            rb1 = *(const float4*)&fcW[(o0 + lr) * 256 + kBase + lo + 32];
        }
        #pragma unroll
        for (int oo = 0; oo < 32; oo++) {
            float2 a2 = *(const float2*)&As[buf][oo][ty * 2];
            float4 bq = *(const float4*)&Bs[buf][oo][tx * 4];
            acc[0][0] = fmaf(a2.x, bq.x, acc[0][0]); acc[0][1] = fmaf(a2.x, bq.y, acc[0][1]);
            acc[0][2] = fmaf(a2.x, bq.z, acc[0][2]); acc[0][3] = fmaf(a2.x, bq.w, acc[0][3]);
            acc[1][0] = fmaf(a2.y, bq.x, acc[1][0]); acc[1][1] = fmaf(a2.y, bq.y, acc[1][1]);
            acc[1][2] = fmaf(a2.y, bq.z, acc[1][2]); acc[1][3] = fmaf(a2.y, bq.w, acc[1][3]);
        }
        if (cI < 15) {
            __syncthreads();
            int nb = buf ^ 1;
            As[nb][lo + 0][lr] = ra.x; As[nb][lo + 1][lr] = ra.y;
            As[nb][lo + 2][lr] = ra.z; As[nb][lo + 3][lr] = ra.w;
            *(float4*)&Bs[nb][lr][lo] = rb0;
            *(float4*)&Bs[nb][lr][lo + 32] = rb1;
            __syncthreads();
        }
    }
    #pragma unroll
    for (int i = 0; i < 2; i++)
        #pragma unroll
        for (int j = 0; j < 4; j++) {
            int idx = (rBase + ty * 2 + i) * 256 + kBase + tx * 4 + j;
            d_Weffc[idx] = acc[i][j] + decWhh[idx];
        }
}

// ========== decoder bias precompute ==========
__global__ __launch_bounds__(256) void dbias_kernel(const float* __restrict__ decWih,
                                                    const float* __restrict__ decBih,
                                                    const float* __restrict__ decBhh,
                                                    const float* __restrict__ fcb) {
    int row = blockIdx.x * 8 + (threadIdx.x >> 5);
    int lane = threadIdx.x & 31;
    float p = 0.f;
    for (int o = lane; o < 512; o += 32)
        p = fmaf(decWih[row * 512 + o], fcb[o], p);
    #pragma unroll
    for (int s = 16; s; s >>= 1) p += __shfl_xor_sync(0xffffffffu, p, s);
    if (lane == 0) {
        float db = decBih[row] + decBhh[row];
        d_db0[row] = db;
        d_dbE[row] = db + p;
    }
}

// ====================== clustered recurrent kernel ========================
__device__ __forceinline__ float sigf(float v) {
    return __fdividef(1.f, 1.f + __expf(-v));
}
__device__ __forceinline__ float tanh_pt(float v) {
    float t = __expf(-2.f * fabsf(v));
    float r = __fdividef(1.f - t, 1.f + t);
    return copysignf(r, v);
}
__device__ __forceinline__ uint32_t smem_u32(const void* p) {
    uint32_t a;
    asm("{ .reg .u64 t; cvta.to.shared.u64 t, %1; cvt.u32.u64 %0, t; }"
        : "=r"(a) : "l"(p));
    return a;
}
__device__ __forceinline__ void st_cluster(uint32_t laddr, uint32_t rnk, float v) {
    uint32_t remote;
    asm volatile("mapa.shared::cluster.u32 %0, %1, %2;"
                 : "=r"(remote) : "r"(laddr), "r"(rnk));
    asm volatile("st.shared::cluster.b32 [%0], %1;"
                 :: "r"(remote), "r"(__float_as_uint(v)) : "memory");
}
__device__ __forceinline__ void arrive_rel(uint32_t laddr, uint32_t rnk) {
    uint32_t remote;
    asm volatile("mapa.shared::cluster.u32 %0, %1, %2;"
                 : "=r"(remote) : "r"(laddr), "r"(rnk));
    asm volatile("mbarrier.arrive.release.cluster.shared::cluster.b64 _, [%0];"
                 :: "r"(remote) : "memory");
}
__device__ __forceinline__ void mbar_wait(uint32_t addr, uint32_t parity) {
    asm volatile(
        "{\n\t.reg .pred P;\n"
        "WL_%=:\n\t"
        "mbarrier.try_wait.parity.acquire.cluster.shared::cta.b64 P, [%0], %1, 0x989680;\n\t"
        "@!P bra WL_%=;\n\t"
        "}" :: "r"(addr), "r"(parity) : "memory");
}
__device__ __forceinline__ void cluster_sync_hw() {
    asm volatile("barrier.cluster.arrive.aligned;" ::: "memory");
    asm volatile("barrier.cluster.wait.aligned;" ::: "memory");
}
__device__ __forceinline__ uint32_t ctarank() {
    uint32_t r;
    asm("mov.u32 %0, %%cluster_ctarank;" : "=r"(r));
    return r;
}

__global__ __launch_bounds__(512, 1) __cluster_dims__(8, 1, 1)
void rec_kernel(const float* __restrict__ encWhh,
                const float* __restrict__ decWhh,
                const float* __restrict__ fcW,
                const float* __restrict__ fcb,
                float* __restrict__ out) {
    __shared__ float hland[4][256];
    __shared__ float sdb0[128];
    __shared__ float sdbE[128];
    __shared__ __align__(8) uint64_t mbar;

    const int tid = threadIdx.x;
    const int w = tid >> 5, l = tid & 31;
    const uint32_t rank = ctarank();
    const int b = blockIdx.x >> 3;
    const int unit0 = (int)rank * 32 + w * 2;

    // init
    if (tid < 256) hland[0][tid] = 0.f;
    if (tid < 128) {
        int g2 = ((tid >> 5) << 8) + (int)rank * 32 + (tid & 31);
        sdb0[tid] = d_db0[g2];
        sdbE[tid] = d_dbE[g2];
    }
    const uint32_t mb = smem_u32(&mbar);
    if (tid == 0)
        asm volatile("mbarrier.init.shared.b64 [%0], 256;" :: "r"(mb) : "memory");

    // encoder weights (8 rows x my 8-k slice)
    float4 wv[8][2];
    #pragma unroll
    for (int ri = 0; ri < 8; ri++) {
        int row = (ri & 3) * 256 + unit0 + (ri >> 2);
        const float4* p4 = (const float4*)(encWhh + row * 256 + l * 8);
        wv[ri][0] = __ldg(p4); wv[ri][1] = __ldg(p4 + 1);
    }
    // pred mapping
    const int fr = tid >> 3, kq = tid & 7;
    const int frg = (int)rank * 64 + fr;
    float fbv = __ldg(&fcb[frg]);
    float4 fw[8];

    const int row_l = (l & 3) * 256 + unit0 + (l >> 2);   // lanes <8
    const int lidx  = (l & 3) * 32 + w * 2 + (l >> 2);
    float gv = 0.f;
    if (l < 8) gv = __ldg(&d_G[(b * 64 + 0) * 1024 + row_l]);

    const uint32_t hl_base = smem_u32(&hland[0][0]);
    float c = 0.f;

    __syncthreads();
    cluster_sync_hw();

    #pragma unroll 1
    for (int t = 0; t < 88; t++) {
        if (t > 0) mbar_wait(mb, (uint32_t)((t - 1) & 1));
        const int cur = t & 3, nxt = (t + 1) & 3;

        // pred for decoder step t-65 (h(t) just became visible)
        if (t >= 65) {
            const float* hp = hland[cur];
            float pa = 0.f;
            #pragma unroll
            for (int j2 = 0; j2 < 8; j2++) {
                float4 hv = *(const float4*)&hp[j2 * 32 + kq * 4];
                pa = fmaf(hv.x, fw[j2].x, pa); pa = fmaf(hv.y, fw[j2].y, pa);
                pa = fmaf(hv.z, fw[j2].z, pa); pa = fmaf(hv.w, fw[j2].w, pa);
            }
            pa += __shfl_xor_sync(0xffffffffu, pa, 1);
            pa += __shfl_xor_sync(0xffffffffu, pa, 2);
            pa += __shfl_xor_sync(0xffffffffu, pa, 4);
            if (kq == 0)
                out[b * (NFLEN * NOUT) + (t - 65) * NOUT + frg] = pa + fbv;
        }

        if (t == 64) {   // switch to decoder: this step uses raw decWhh
            #pragma unroll
            for (int ri = 0; ri < 8; ri++) {
                int row = (ri & 3) * 256 + unit0 + (ri >> 2);
                const float4* p4 = (const float4*)(decWhh + row * 256 + l * 8);
                wv[ri][0] = __ldg(p4); wv[ri][1] = __ldg(p4 + 1);
            }
            #pragma unroll
            for (int j2 = 0; j2 < 8; j2++)
                fw[j2] = __ldg((const float4*)&fcW[frg * 256 + j2 * 32 + kq * 4]);
        }

        // gate dots: 8 rows, my k-slice
        float4 h0 = *(const float4*)&hland[cur][l * 8];
        float4 h1 = *(const float4*)&hland[cur][l * 8 + 4];
        float acc[8];
        #pragma unroll
        for (int ri = 0; ri < 8; ri++) {
            float a = h0.x * wv[ri][0].x;
            a = fmaf(h0.y, wv[ri][0].y, a); a = fmaf(h0.z, wv[ri][0].z, a);
            a = fmaf(h0.w, wv[ri][0].w, a); a = fmaf(h1.x, wv[ri][1].x, a);
            a = fmaf(h1.y, wv[ri][1].y, a); a = fmaf(h1.z, wv[ri][1].z, a);
            a = fmaf(h1.w, wv[ri][1].w, a);
            acc[ri] = a;
        }
        #pragma unroll
        for (int ri = 0; ri < 8; ri++) {
            #pragma unroll
            for (int s = 16; s; s >>= 1)
                acc[ri] += __shfl_xor_sync(0xffffffffu, acc[ri], s);
        }
        int sel = l & 7;
        float rs = acc[0];
        if (sel == 1) rs = acc[1]; if (sel == 2) rs = acc[2];
        if (sel == 3) rs = acc[3]; if (sel == 4) rs = acc[4];
        if (sel == 5) rs = acc[5]; if (sel == 6) rs = acc[6];
        if (sel == 7) rs = acc[7];

        if (l < 8) {
            if (t < 64)       rs += gv;
            else if (t == 64) rs += sdb0[lidx];
            else              rs += sdbE[lidx];
        }
        if (l < 8 && t < 63) gv = __ldg(&d_G[(b * 64 + t + 1) * 1024 + row_l]);

        int base = l & 4;
        float gi = __shfl_sync(0xffffffffu, rs, base + 0);
        float gf = __shfl_sync(0xffffffffu, rs, base + 1);
        float gg = __shfl_sync(0xffffffffu, rs, base + 2);
        float go = __shfl_sync(0xffffffffu, rs, base + 3);

        if ((l & 27) == 0) {   // lanes 0 and 4
            c = sigf(gf) * c + sigf(gi) * tanh_pt(gg);
            float hh = sigf(go) * tanh_pt(c);
            int gu = unit0 + (l >> 2);
            uint32_t la = hl_base + (uint32_t)((nxt << 8) + gu) * 4u;
            #pragma unroll
            for (uint32_t p = 0; p < 8; p++) st_cluster(la, p, hh);
            #pragma unroll
            for (uint32_t p = 0; p < 8; p++) arrive_rel(mb, p);
        }
        if (t == 64) {   // now load combined weights for t>=65
            #pragma unroll
            for (int ri = 0; ri < 8; ri++) {
                int row = (ri & 3) * 256 + unit0 + (ri >> 2);
                const float4* p4 = (const float4*)(d_Weffc + row * 256 + l * 8);
                wv[ri][0] = __ldg(p4); wv[ri][1] = __ldg(p4 + 1);
            }
        }
    }

    // final pred (dt=23): h(88) in slot 0
    mbar_wait(mb, 1u);
    {
        const float* hp = hland[0];
        float pa = 0.f;
        #pragma unroll
        for (int j2 = 0; j2 < 8; j2++) {
            float4 hv = *(const float4*)&hp[j2 * 32 + kq * 4];
            pa = fmaf(hv.x, fw[j2].x, pa); pa = fmaf(hv.y, fw[j2].y, pa);
            pa = fmaf(hv.z, fw[j2].z, pa); pa = fmaf(hv.w, fw[j2].w, pa);
        }
        pa += __shfl_xor_sync(0xffffffffu, pa, 1);
        pa += __shfl_xor_sync(0xffffffffu, pa, 2);
        pa += __shfl_xor_sync(0xffffffffu, pa, 4);
        if (kq == 0)
            out[b * (NFLEN * NOUT) + 23 * NOUT + frg] = pa + fbv;
    }
    cluster_sync_hw();   // nobody exits while peers may still read our smem
}

// ============================== launcher ==================================
extern "C" void kernel_launch(void* const* d_in, const int* in_sizes, int n_in,
                              void* d_out, int out_size) {
    const float* x      = (const float*)d_in[0];
    const float* gatW   = (const float*)d_in[2];
    const float* gata   = (const float*)d_in[3];
    const float* encWih = (const float*)d_in[4];
    const float* encWhh = (const float*)d_in[5];
    const float* encbih = (const float*)d_in[6];
    const float* encbhh = (const float*)d_in[7];
    const float* decWih = (const float*)d_in[8];
    const float* decWhh = (const float*)d_in[9];
    const float* decbih = (const float*)d_in[10];
    const float* decbhh = (const float*)d_in[11];
    const float* fcW    = (const float*)d_in[12];
    const float* fcb    = (const float*)d_in[13];
    float* out = (float*)d_out;

    gat_kernel<<<NB * NT, 512>>>(x, gatW, gata);
    wef_gemm<<<dim3(4, 32), 256>>>(decWih, fcW, decWhh);
    dbias_kernel<<<128, 256>>>(decWih, decbih, decbhh, fcb);
    enc_gemm<<<dim3(16, 8), 256>>>(encWih, encbih, encbhh);
    rec_kernel<<<64, 512>>>(encWhh, decWhh, fcW, fcb, out);
}

// round 11
// speedup vs baseline: 2.0586x; 2.0586x over previous
#include <cuda_runtime.h>
#include <math.h>
#include <stdint.h>

#define NB 8
#define NT 64
#define NN 512
#define NH 256
#define NOUT 512
#define NFLEN 24

// ---------------- device scratch (no allocations allowed) ----------------
__device__ float d_xg[NB * NT * NN];          // GAT output  [B,T,N]
__device__ float d_G[NB * NT * 4 * NH];       // enc input preacts (+bias)
__device__ float d_Weffc[4 * NH * NH];        // dec_Wih @ fc_W + decWhh
__device__ float d_db0[4 * NH];               // dec bias (dt==0)
__device__ float d_dbE[4 * NH];               // dec bias + decWih@fcb

// ============================= GAT kernel =================================
__global__ __launch_bounds__(512) void gat_kernel(const float* __restrict__ x,
                                                  const float* __restrict__ gatW,
                                                  const float* __restrict__ gata) {
    __shared__ float  sk[512];
    __shared__ float  sf[512];
    __shared__ float4 ssum[512];
    __shared__ float  sred[16];
    __shared__ float4 swt[16];
    __shared__ float4 swo[16];

    int bt = blockIdx.x, tid = threadIdx.x;
    int lane = tid & 31, wid = tid >> 5;
    float W = gatW[0], a0 = gata[0], a1 = gata[1];
    float fi = x[bt * NN + tid] * W;
    float v = a1 * fi;

    float m = v;
    #pragma unroll
    for (int s = 16; s; s >>= 1) m = fmaxf(m, __shfl_xor_sync(0xffffffffu, m, s));
    if (lane == 0) sred[wid] = m;
    __syncthreads();
    if (tid < 32) {
        float t2 = (tid < 16) ? sred[tid] : -3.4e38f;
        #pragma unroll
        for (int s = 8; s; s >>= 1) t2 = fmaxf(t2, __shfl_xor_sync(0xffffffffu, t2, s));
        if (tid == 0) sred[0] = t2;
    }
    sk[tid] = v;
    sf[tid] = fi;
    __syncthreads();
    float vmax = sred[0];

    for (int k = 2; k <= 512; k <<= 1) {
        for (int j = k >> 1; j > 0; j >>= 1) {
            int ixj = tid ^ j;
            if (ixj > tid) {
                float ka = sk[tid], kb = sk[ixj];
                bool up = ((tid & k) == 0);
                if ((ka > kb) == up) {
                    sk[tid] = kb; sk[ixj] = ka;
                    float t = sf[tid]; sf[tid] = sf[ixj]; sf[ixj] = t;
                }
            }
            __syncthreads();
        }
    }

    float vs = sk[tid], fs = sf[tid];
    float p1 = __expf(vs - vmax);
    float p2 = __expf(0.2f * (vs - vmax));
    float4 pl = make_float4(p1, p2, fs * p1, fs * p2);

    float4 s4 = pl;
    #pragma unroll
    for (int off = 1; off < 32; off <<= 1) {
        float nx = __shfl_up_sync(0xffffffffu, s4.x, off);
        float ny = __shfl_up_sync(0xffffffffu, s4.y, off);
        float nz = __shfl_up_sync(0xffffffffu, s4.z, off);
        float nw = __shfl_up_sync(0xffffffffu, s4.w, off);
        if (lane >= off) { s4.x += nx; s4.y += ny; s4.z += nz; s4.w += nw; }
    }
    if (lane == 31) swt[wid] = s4;
    __syncthreads();
    if (tid < 16) {
        float4 t4 = swt[tid];
        float4 c4 = t4;
        #pragma unroll
        for (int off = 1; off < 16; off <<= 1) {
            float nx = __shfl_up_sync(0x0000ffffu, c4.x, off);
            float ny = __shfl_up_sync(0x0000ffffu, c4.y, off);
            float nz = __shfl_up_sync(0x0000ffffu, c4.z, off);
            float nw = __shfl_up_sync(0x0000ffffu, c4.w, off);
            if (tid >= off) { c4.x += nx; c4.y += ny; c4.z += nz; c4.w += nw; }
        }
        swo[tid] = make_float4(c4.x - t4.x, c4.y - t4.y, c4.z - t4.z, c4.w - t4.w);
    }
    __syncthreads();
    float4 wo = swo[wid];
    float4 excl = make_float4(s4.x - pl.x + wo.x, s4.y - pl.y + wo.y,
                              s4.z - pl.z + wo.z, s4.w - pl.w + wo.w);
    ssum[tid] = excl;
    __syncthreads();
    float4 T = make_float4(swo[15].x + swt[15].x, swo[15].y + swt[15].y,
                           swo[15].z + swt[15].z, swo[15].w + swt[15].w);

    float c = a0 * fi, thr = -c;
    int lo = 0, hi = 512;
    #pragma unroll
    for (int it = 0; it < 9; it++) {
        int mid = (lo + hi) >> 1;
        bool g = sk[mid] > thr;
        hi = g ? mid : hi;
        lo = g ? lo : mid + 1;
    }
    float4 E = (lo < 512) ? ssum[lo] : T;
    float A  = T.z - E.z;
    float Cs = T.x - E.x;
    float D  = E.y;
    float Bs = E.w;

    float s = c + vmax;
    float M = s > 0.f ? s : 0.2f * s;
    float alpha = __expf(s - M);
    float beta  = __expf(0.2f * s - M);
    float r = (alpha * A + beta * Bs) / (alpha * Cs + beta * D);
    d_xg[bt * NN + tid] = r > 0.f ? r : 0.f;
}

// ======================= enc input GEMM (+bias) ===========================
__global__ __launch_bounds__(256) void enc_gemm(const float* __restrict__ Wih,
                                                const float* __restrict__ bih,
                                                const float* __restrict__ bhh) {
    __shared__ float As[2][32][68];
    __shared__ float Bs[2][32][68];
    const int tid = threadIdx.x;
    const int tx = tid & 15, ty = tid >> 4;
    const int mBase = blockIdx.y * 64, rBase = blockIdx.x * 64;
    const int lm = tid >> 3, lk = (tid & 7) * 4;
    float acc[4][4] = {};
    float4 ra[2], rb[2];

    #pragma unroll
    for (int h = 0; h < 2; h++) {
        int mm = lm + h * 32;
        float4 av = *(const float4*)&d_xg[(mBase + mm) * 512 + lk];
        As[0][lk + 0][mm] = av.x; As[0][lk + 1][mm] = av.y;
        As[0][lk + 2][mm] = av.z; As[0][lk + 3][mm] = av.w;
        float4 bv = *(const float4*)&Wih[(rBase + mm) * 512 + lk];
        Bs[0][lk + 0][mm] = bv.x; Bs[0][lk + 1][mm] = bv.y;
        Bs[0][lk + 2][mm] = bv.z; Bs[0][lk + 3][mm] = bv.w;
    }
    __syncthreads();

    #pragma unroll 1
    for (int cI = 0; cI < 16; cI++) {
        int buf = cI & 1;
        if (cI < 15) {
            int k0 = (cI + 1) * 32;
            #pragma unroll
            for (int h = 0; h < 2; h++) {
                int mm = lm + h * 32;
                ra[h] = *(const float4*)&d_xg[(mBase + mm) * 512 + k0 + lk];
                rb[h] = *(const float4*)&Wih[(rBase + mm) * 512 + k0 + lk];
            }
        }
        #pragma unroll
        for (int kk = 0; kk < 32; kk++) {
            float4 a = *(const float4*)&As[buf][kk][ty * 4];
            float4 bq = *(const float4*)&Bs[buf][kk][tx * 4];
            acc[0][0] = fmaf(a.x, bq.x, acc[0][0]); acc[0][1] = fmaf(a.x, bq.y, acc[0][1]);
            acc[0][2] = fmaf(a.x, bq.z, acc[0][2]); acc[0][3] = fmaf(a.x, bq.w, acc[0][3]);
            acc[1][0] = fmaf(a.y, bq.x, acc[1][0]); acc[1][1] = fmaf(a.y, bq.y, acc[1][1]);
            acc[1][2] = fmaf(a.y, bq.z, acc[1][2]); acc[1][3] = fmaf(a.y, bq.w, acc[1][3]);
            acc[2][0] = fmaf(a.z, bq.x, acc[2][0]); acc[2][1] = fmaf(a.z, bq.y, acc[2][1]);
            acc[2][2] = fmaf(a.z, bq.z, acc[2][2]); acc[2][3] = fmaf(a.z, bq.w, acc[2][3]);
            acc[3][0] = fmaf(a.w, bq.x, acc[3][0]); acc[3][1] = fmaf(a.w, bq.y, acc[3][1]);
            acc[3][2] = fmaf(a.w, bq.z, acc[3][2]); acc[3][3] = fmaf(a.w, bq.w, acc[3][3]);
        }
        if (cI < 15) {
            __syncthreads();
            int nb = buf ^ 1;
            #pragma unroll
            for (int h = 0; h < 2; h++) {
                int mm = lm + h * 32;
                As[nb][lk + 0][mm] = ra[h].x; As[nb][lk + 1][mm] = ra[h].y;
                As[nb][lk + 2][mm] = ra[h].z; As[nb][lk + 3][mm] = ra[h].w;
                Bs[nb][lk + 0][mm] = rb[h].x; Bs[nb][lk + 1][mm] = rb[h].y;
                Bs[nb][lk + 2][mm] = rb[h].z; Bs[nb][lk + 3][mm] = rb[h].w;
            }
            __syncthreads();
        }
    }
    #pragma unroll
    for (int i = 0; i < 4; i++) {
        int mm = mBase + ty * 4 + i;
        #pragma unroll
        for (int j = 0; j < 4; j++) {
            int r = rBase + tx * 4 + j;
            d_G[mm * 1024 + r] = acc[i][j] + bih[r] + bhh[r];
        }
    }
}

// ====== Weffc GEMM: dec_Wih[1024,512] @ fc_W[512,256] + decWhh ============
__global__ __launch_bounds__(256) void wef_gemm(const float* __restrict__ decWih,
                                                const float* __restrict__ fcW,
                                                const float* __restrict__ decWhh) {
    __shared__ float As[2][32][36];
    __shared__ float Bs[2][32][68];
    const int tid = threadIdx.x;
    const int tx = tid & 15, ty = tid >> 4;
    const int kBase = blockIdx.x * 64, rBase = blockIdx.y * 32;
    const int lr = tid >> 3, lo = (tid & 7) * 4;
    float acc[2][4] = {};
    float4 ra, rb0, rb1;

    {
        float4 av = *(const float4*)&decWih[(rBase + lr) * 512 + lo];
        As[0][lo + 0][lr] = av.x; As[0][lo + 1][lr] = av.y;
        As[0][lo + 2][lr] = av.z; As[0][lo + 3][lr] = av.w;
        *(float4*)&Bs[0][lr][lo] = *(const float4*)&fcW[lr * 256 + kBase + lo];
        *(float4*)&Bs[0][lr][lo + 32] = *(const float4*)&fcW[lr * 256 + kBase + lo + 32];
    }
    __syncthreads();

    #pragma unroll 1
    for (int cI = 0; cI < 16; cI++) {
        int buf = cI & 1;
        if (cI < 15) {
            int o0 = (cI + 1) * 32;
            ra  = *(const float4*)&decWih[(rBase + lr) * 512 + o0 + lo];
            rb0 = *(const float4*)&fcW[(o0 + lr) * 256 + kBase + lo];
            rb1 = *(const float4*)&fcW[(o0 + lr) * 256 + kBase + lo + 32];
        }
        #pragma unroll
        for (int oo = 0; oo < 32; oo++) {
            float2 a2 = *(const float2*)&As[buf][oo][ty * 2];
            float4 bq = *(const float4*)&Bs[buf][oo][tx * 4];
            acc[0][0] = fmaf(a2.x, bq.x, acc[0][0]); acc[0][1] = fmaf(a2.x, bq.y, acc[0][1]);
            acc[0][2] = fmaf(a2.x, bq.z, acc[0][2]); acc[0][3] = fmaf(a2.x, bq.w, acc[0][3]);
            acc[1][0] = fmaf(a2.y, bq.x, acc[1][0]); acc[1][1] = fmaf(a2.y, bq.y, acc[1][1]);
            acc[1][2] = fmaf(a2.y, bq.z, acc[1][2]); acc[1][3] = fmaf(a2.y, bq.w, acc[1][3]);
        }
        if (cI < 15) {
            __syncthreads();
            int nb = buf ^ 1;
            As[nb][lo + 0][lr] = ra.x; As[nb][lo + 1][lr] = ra.y;
            As[nb][lo + 2][lr] = ra.z; As[nb][lo + 3][lr] = ra.w;
            *(float4*)&Bs[nb][lr][lo] = rb0;
            *(float4*)&Bs[nb][lr][lo + 32] = rb1;
            __syncthreads();
        }
    }
    #pragma unroll
    for (int i = 0; i < 2; i++)
        #pragma unroll
        for (int j = 0; j < 4; j++) {
            int idx = (rBase + ty * 2 + i) * 256 + kBase + tx * 4 + j;
            d_Weffc[idx] = acc[i][j] + decWhh[idx];
        }
}

// ========== decoder bias precompute ==========
__global__ __launch_bounds__(256) void dbias_kernel(const float* __restrict__ decWih,
                                                    const float* __restrict__ decBih,
                                                    const float* __restrict__ decBhh,
                                                    const float* __restrict__ fcb) {
    int row = blockIdx.x * 8 + (threadIdx.x >> 5);
    int lane = threadIdx.x & 31;
    float p = 0.f;
    for (int o = lane; o < 512; o += 32)
        p = fmaf(decWih[row * 512 + o], fcb[o], p);
    #pragma unroll
    for (int s = 16; s; s >>= 1) p += __shfl_xor_sync(0xffffffffu, p, s);
    if (lane == 0) {
        float db = decBih[row] + decBhh[row];
        d_db0[row] = db;
        d_dbE[row] = db + p;
    }
}

// ====================== clustered recurrent kernel ========================
__device__ __forceinline__ float sigf(float v) {
    return __fdividef(1.f, 1.f + __expf(-v));
}
__device__ __forceinline__ float tanh_pt(float v) {
    float t = __expf(-2.f * fabsf(v));
    float r = __fdividef(1.f - t, 1.f + t);
    return copysignf(r, v);
}
__device__ __forceinline__ uint32_t smem_u32(const void* p) {
    uint32_t a;
    asm("{ .reg .u64 t; cvta.to.shared.u64 t, %1; cvt.u32.u64 %0, t; }"
        : "=r"(a) : "l"(p));
    return a;
}
__device__ __forceinline__ void st_cluster(uint32_t laddr, uint32_t rnk, float v) {
    uint32_t remote;
    asm volatile("mapa.shared::cluster.u32 %0, %1, %2;"
                 : "=r"(remote) : "r"(laddr), "r"(rnk));
    asm volatile("st.shared::cluster.b32 [%0], %1;"
                 :: "r"(remote), "r"(__float_as_uint(v)) : "memory");
}
__device__ __forceinline__ void cluster_sync_hw() {
    asm volatile("barrier.cluster.arrive.aligned;" ::: "memory");
    asm volatile("barrier.cluster.wait.aligned;" ::: "memory");
}
__device__ __forceinline__ uint32_t ctarank() {
    uint32_t r;
    asm("mov.u32 %0, %%cluster_ctarank;" : "=r"(r));
    return r;
}

__global__ __launch_bounds__(512, 1) __cluster_dims__(8, 1, 1)
void rec_kernel(const float* __restrict__ encWhh,
                const float* __restrict__ decWhh,
                const float* __restrict__ fcW,
                const float* __restrict__ fcb,
                float* __restrict__ out) {
    __shared__ float sG[64][128];      // this CTA's enc preacts, all 64 steps
    __shared__ float hland[4][256];
    __shared__ float sdb0[128];
    __shared__ float sdbE[128];

    const int tid = threadIdx.x;
    const int w = tid >> 5, l = tid & 31;
    const uint32_t rank = ctarank();
    const int b = blockIdx.x >> 3;
    const int u0 = (int)rank * 32 + w * 2;

    // Row held by this lane after the butterfly reduction:
    // R = ((l&1)<<2) | (l&2) | ((l>>2)&1); gate = R>>1 (i,f,g,o), unit = R&1.
    // lanes: 0->i/u0 1->g/u0 2->f/u0 3->o/u0 4->i/u1 5->g/u1 6->f/u1 7->o/u1
    const int R = ((l & 1) << 2) | (l & 2) | ((l >> 2) & 1);
    const int lrl = (R >> 1) * 32 + w * 2 + (R & 1);   // local row (bias/G idx)

    // ---- stage d_G slice into smem: sG[t][lr], lr = gate*32 + unitoff ----
    for (int i = tid; i < 64 * 128; i += 512) {
        int t = i >> 7, lr = i & 127;
        sG[t][lr] = d_G[(b * 64 + t) * 1024 + (lr >> 5) * 256 + (int)rank * 32 + (lr & 31)];
    }
    if (tid < 256) hland[0][tid] = 0.f;
    if (tid < 128) {
        int gr2 = (tid >> 5) * 256 + (int)rank * 32 + (tid & 31);
        sdb0[tid] = d_db0[gr2];
        sdbE[tid] = d_dbE[gr2];
    }

    // ---- encoder recurrent weights: 8 rows x my 8-wide k slice ----
    float4 wv[8][2];
    #pragma unroll
    for (int j = 0; j < 8; j++) {
        int gr = (j >> 1) * 256 + u0 + (j & 1);
        const float4* p4 = (const float4*)(encWhh + gr * 256 + l * 8);
        wv[j][0] = __ldg(p4); wv[j][1] = __ldg(p4 + 1);
    }
    // pred mapping
    const int fr = tid >> 3, kq = tid & 7;
    const int frg = (int)rank * 64 + fr;
    float fbv = __ldg(&fcb[frg]);
    float4 fw[8];

    const uint32_t hl_base = smem_u32(&hland[0][0]);
    float c = 0.f;                   // cell state (lanes 0,4 of each warp)

    __syncthreads();
    cluster_sync_hw();

    #pragma unroll 1
    for (int t = 0; t < 88; t++) {
        const int cur = t & 3, nxt = (t + 1) & 3;

        // pred for decoder step t-65 (h(t) became visible at last barrier)
        if (t >= 65) {
            const float* hp = hland[cur];
            float pa = 0.f;
            #pragma unroll
            for (int j2 = 0; j2 < 8; j2++) {
                float4 hv = *(const float4*)&hp[j2 * 32 + kq * 4];
                pa = fmaf(hv.x, fw[j2].x, pa); pa = fmaf(hv.y, fw[j2].y, pa);
                pa = fmaf(hv.z, fw[j2].z, pa); pa = fmaf(hv.w, fw[j2].w, pa);
            }
            pa += __shfl_xor_sync(0xffffffffu, pa, 1);
            pa += __shfl_xor_sync(0xffffffffu, pa, 2);
            pa += __shfl_xor_sync(0xffffffffu, pa, 4);
            if (kq == 0)
                out[b * (NFLEN * NOUT) + (t - 65) * NOUT + frg] = pa + fbv;
        }

        if (t == 64) {   // decoder step 0 uses raw decWhh; also load fc rows
            #pragma unroll
            for (int j = 0; j < 8; j++) {
                int gr = (j >> 1) * 256 + u0 + (j & 1);
                const float4* p4 = (const float4*)(decWhh + gr * 256 + l * 8);
                wv[j][0] = __ldg(p4); wv[j][1] = __ldg(p4 + 1);
            }
            #pragma unroll
            for (int j2 = 0; j2 < 8; j2++)
                fw[j2] = __ldg((const float4*)&fcW[frg * 256 + j2 * 32 + kq * 4]);
        }

        // bias for my final row (read early, hides LDS latency)
        float bias = (t < 64) ? sG[t][lrl] : ((t == 64) ? sdb0[lrl] : sdbE[lrl]);

        // 8 row-dots over my 8-k slice
        float4 h0 = *(const float4*)&hland[cur][l * 8];
        float4 h1 = *(const float4*)&hland[cur][l * 8 + 4];
        float acc[8];
        #pragma unroll
        for (int j = 0; j < 8; j++) {
            float a = h0.x * wv[j][0].x;
            a = fmaf(h0.y, wv[j][0].y, a); a = fmaf(h0.z, wv[j][0].z, a);
            a = fmaf(h0.w, wv[j][0].w, a); a = fmaf(h1.x, wv[j][1].x, a);
            a = fmaf(h1.y, wv[j][1].y, a); a = fmaf(h1.z, wv[j][1].z, a);
            a = fmaf(h1.w, wv[j][1].w, a);
            acc[j] = a;
        }
        // multi-value butterfly: 8 sums in 9 shfls
        {
            const bool b0 = (l & 1), b1 = (l & 2), b2 = (l & 4);
            float na[4];
            #pragma unroll
            for (int j = 0; j < 4; j++) {
                float send = b0 ? acc[j] : acc[j + 4];
                float keep = b0 ? acc[j + 4] : acc[j];
                na[j] = keep + __shfl_xor_sync(0xffffffffu, send, 1);
            }
            float nb[2];
            #pragma unroll
            for (int j = 0; j < 2; j++) {
                float send = b1 ? na[j] : na[j + 2];
                float keep = b1 ? na[j + 2] : na[j];
                nb[j] = keep + __shfl_xor_sync(0xffffffffu, send, 2);
            }
            float send = b2 ? nb[0] : nb[1];
            float keep = b2 ? nb[1] : nb[0];
            acc[0] = keep + __shfl_xor_sync(0xffffffffu, send, 4);
            acc[0] += __shfl_xor_sync(0xffffffffu, acc[0], 8);
            acc[0] += __shfl_xor_sync(0xffffffffu, acc[0], 16);
        }
        float aval = acc[0] + bias;

        // lane base+0 holds gate i, base+1 g, base+2 f, base+3 o (base = l&4)
        int base = l & 4;
        float gi = __shfl_sync(0xffffffffu, aval, base + 0);
        float gg = __shfl_sync(0xffffffffu, aval, base + 1);
        float gf = __shfl_sync(0xffffffffu, aval, base + 2);
        float go = __shfl_sync(0xffffffffu, aval, base + 3);

        if ((l & 27) == 0) {   // lanes 0 and 4: units u0, u0+1
            c = sigf(gf) * c + sigf(gi) * tanh_pt(gg);
            float hh = sigf(go) * tanh_pt(c);
            int gu = u0 + (l >> 2);
            uint32_t la = hl_base + (uint32_t)((nxt << 8) + gu) * 4u;
            #pragma unroll
            for (uint32_t p = 0; p < 8; p++) st_cluster(la, p, hh);
        }

        if (t == 64) {   // steps t>=65 use combined Weffc (dec_Wih@fc_W + decWhh)
            #pragma unroll
            for (int j = 0; j < 8; j++) {
                int gr = (j >> 1) * 256 + u0 + (j & 1);
                const float4* p4 = (const float4*)(d_Weffc + gr * 256 + l * 8);
                wv[j][0] = __ldg(p4); wv[j][1] = __ldg(p4 + 1);
            }
        }
        cluster_sync_hw();   // release: stores above visible cluster-wide
    }

    // final pred (dt=23): h(88) in slot 0
    {
        const float* hp = hland[0];
        float pa = 0.f;
        #pragma unroll
        for (int j2 = 0; j2 < 8; j2++) {
            float4 hv = *(const float4*)&hp[j2 * 32 + kq * 4];
            pa = fmaf(hv.x, fw[j2].x, pa); pa = fmaf(hv.y, fw[j2].y, pa);
            pa = fmaf(hv.z, fw[j2].z, pa); pa = fmaf(hv.w, fw[j2].w, pa);
        }
        pa += __shfl_xor_sync(0xffffffffu, pa, 1);
        pa += __shfl_xor_sync(0xffffffffu, pa, 2);
        pa += __shfl_xor_sync(0xffffffffu, pa, 4);
        if (kq == 0)
            out[b * (NFLEN * NOUT) + 23 * NOUT + frg] = pa + fbv;
    }
    cluster_sync_hw();   // nobody exits while peers may still read our smem
}

// ============================== launcher ==================================
extern "C" void kernel_launch(void* const* d_in, const int* in_sizes, int n_in,
                              void* d_out, int out_size) {
    const float* x      = (const float*)d_in[0];
    const float* gatW   = (const float*)d_in[2];
    const float* gata   = (const float*)d_in[3];
    const float* encWih = (const float*)d_in[4];
    const float* encWhh = (const float*)d_in[5];
    const float* encbih = (const float*)d_in[6];
    const float* encbhh = (const float*)d_in[7];
    const float* decWih = (const float*)d_in[8];
    const float* decWhh = (const float*)d_in[9];
    const float* decbih = (const float*)d_in[10];
    const float* decbhh = (const float*)d_in[11];
    const float* fcW    = (const float*)d_in[12];
    const float* fcb    = (const float*)d_in[13];
    float* out = (float*)d_out;

    gat_kernel<<<NB * NT, 512>>>(x, gatW, gata);
    wef_gemm<<<dim3(4, 32), 256>>>(decWih, fcW, decWhh);
    dbias_kernel<<<128, 256>>>(decWih, decbih, decbhh, fcb);
    enc_gemm<<<dim3(16, 8), 256>>>(encWih, encbih, encbhh);
    rec_kernel<<<64, 512>>>(encWhh, decWhh, fcW, fcb, out);
}